// round 1
// baseline (speedup 1.0000x reference)
#include <cuda_runtime.h>
#include <cstdint>

#define DFEAT 64
#define NREL 16
#define NCOLS 1088   // (NREL+1)*64 : col 0..63 = self (sw), 64+r*64+j = W[r][:,j]
#define NNODE_MAX 100000

typedef unsigned long long u64;

// Scratch (allocation-free, __device__ globals)
__device__ float g_Y[(size_t)NNODE_MAX * NCOLS];      // ~435 MB
__device__ float g_h[(size_t)NNODE_MAX * DFEAT];      // layer-1 activations
__device__ float g_Wcat[DFEAT * NCOLS];               // packed [k][c] weights

// ---------------------------------------------------------------------------
// packed f32x2 helpers (Blackwell 2x fp32)
// ---------------------------------------------------------------------------
__device__ __forceinline__ u64 pack2(float lo, float hi) {
    u64 r;
    asm("mov.b64 %0, {%1, %2};" : "=l"(r) : "f"(lo), "f"(hi));
    return r;
}
__device__ __forceinline__ void unpack2(u64 v, float& lo, float& hi) {
    asm("mov.b64 {%0, %1}, %2;" : "=f"(lo), "=f"(hi) : "l"(v));
}
__device__ __forceinline__ void fma2(u64& d, u64 a, u64 b) {
    asm("fma.rn.f32x2 %0, %1, %2, %0;" : "+l"(d) : "l"(a), "l"(b));
}

// ---------------------------------------------------------------------------
// Pack Wcat[k][c]: c<64 -> sw[k,c]; else r=(c-64)/64, j=(c-64)%64 -> W[r,k,j]
// ---------------------------------------------------------------------------
__global__ void pack_w(const float* __restrict__ W, const float* __restrict__ sw) {
    int idx = blockIdx.x * blockDim.x + threadIdx.x;
    if (idx >= DFEAT * NCOLS) return;
    int k = idx / NCOLS;
    int c = idx - k * NCOLS;
    float v;
    if (c < DFEAT) {
        v = sw[k * DFEAT + c];
    } else {
        int rc = c - DFEAT;
        int r = rc >> 6, j = rc & 63;
        v = W[r * DFEAT * DFEAT + k * DFEAT + j];
    }
    g_Wcat[idx] = v;
}

// ---------------------------------------------------------------------------
// GEMM: Y[N,1088] = A[N,64] @ Wcat[64,1088]
// block: 128 rows x 64 cols, 128 threads, 8x8 microtile, packed fma.rn.f32x2
// ---------------------------------------------------------------------------
__global__ __launch_bounds__(128, 4) void gemm_xw(const float* __restrict__ A, int N) {
    __shared__ float As[DFEAT][128];   // [k][m] 32 KB
    __shared__ float Bs[DFEAT][64];    // [k][j] 16 KB
    const int t  = threadIdx.x;
    const int n0 = blockIdx.x * 128;
    const int c0 = blockIdx.y * 64;

    // Load A: thread t loads full K-row of node n0+t (clamped), store transposed
    {
        int n  = n0 + t;
        int nn = n < N ? n : N - 1;
        const float4* arow = (const float4*)(A + (size_t)nn * DFEAT);
#pragma unroll
        for (int q = 0; q < 16; q++) {
            float4 v = arow[q];
            As[q * 4 + 0][t] = v.x;
            As[q * 4 + 1][t] = v.y;
            As[q * 4 + 2][t] = v.z;
            As[q * 4 + 3][t] = v.w;
        }
    }
    // Load B tile: 64x64 floats = 1024 float4, 8 per thread
#pragma unroll
    for (int i = 0; i < 8; i++) {
        int idx = t + i * 128;
        int k = idx >> 4, j4 = idx & 15;
        *(float4*)&Bs[k][j4 * 4] =
            *(const float4*)(g_Wcat + k * NCOLS + c0 + j4 * 4);
    }
    __syncthreads();

    const int r = t >> 3;   // 0..15 -> rows r*8 .. r*8+7 (as 4 m-pairs)
    const int c = t & 7;    // 0..7  -> cols c*8 .. c*8+7

    u64 acc[4][8];
#pragma unroll
    for (int i = 0; i < 4; i++)
#pragma unroll
        for (int j = 0; j < 8; j++) acc[i][j] = 0ULL;

#pragma unroll 8
    for (int k = 0; k < DFEAT; k++) {
        const u64* ap = (const u64*)&As[k][r * 8];   // 32B-aligned m-pairs
        u64 a2[4];
#pragma unroll
        for (int i = 0; i < 4; i++) a2[i] = ap[i];
        float4 bv0 = *(const float4*)&Bs[k][c * 8];
        float4 bv1 = *(const float4*)&Bs[k][c * 8 + 4];
        u64 b2[8];
        b2[0] = pack2(bv0.x, bv0.x); b2[1] = pack2(bv0.y, bv0.y);
        b2[2] = pack2(bv0.z, bv0.z); b2[3] = pack2(bv0.w, bv0.w);
        b2[4] = pack2(bv1.x, bv1.x); b2[5] = pack2(bv1.y, bv1.y);
        b2[6] = pack2(bv1.z, bv1.z); b2[7] = pack2(bv1.w, bv1.w);
#pragma unroll
        for (int i = 0; i < 4; i++)
#pragma unroll
            for (int j = 0; j < 8; j++) fma2(acc[i][j], a2[i], b2[j]);
    }

    // Store: acc[i][j] holds rows (r*8+2i, r*8+2i+1), col c*8+j
#pragma unroll
    for (int i = 0; i < 4; i++) {
        float lo[8], hi[8];
#pragma unroll
        for (int j = 0; j < 8; j++) unpack2(acc[i][j], lo[j], hi[j]);
        int row0 = n0 + r * 8 + i * 2;
        if (row0 < N) {
            float* yp = g_Y + (size_t)row0 * NCOLS + c0 + c * 8;
            *(float4*)yp       = make_float4(lo[0], lo[1], lo[2], lo[3]);
            *(float4*)(yp + 4) = make_float4(lo[4], lo[5], lo[6], lo[7]);
        }
        if (row0 + 1 < N) {
            float* yp = g_Y + (size_t)(row0 + 1) * NCOLS + c0 + c * 8;
            *(float4*)yp       = make_float4(hi[0], hi[1], hi[2], hi[3]);
            *(float4*)(yp + 4) = make_float4(hi[4], hi[5], hi[6], hi[7]);
        }
    }
}

// ---------------------------------------------------------------------------
// init: out = Y_self + b (+ x if residual)
// ---------------------------------------------------------------------------
__global__ void init_layer(const float* __restrict__ x, const float* __restrict__ b,
                           float* __restrict__ out, int total4, int residual) {
    int idx4 = blockIdx.x * blockDim.x + threadIdx.x;
    if (idx4 >= total4) return;
    int n  = idx4 >> 4;          // node
    int j4 = idx4 & 15;          // float4 within feature row
    float4 y  = *(const float4*)(g_Y + (size_t)n * NCOLS + j4 * 4);
    float4 bb = *(const float4*)(b + j4 * 4);
    float4 v = make_float4(y.x + bb.x, y.y + bb.y, y.z + bb.z, y.w + bb.w);
    if (residual) {
        float4 xv = *(const float4*)(x + (size_t)idx4 * 4);
        v.x += xv.x; v.y += xv.y; v.z += xv.z; v.w += xv.w;
    }
    *(float4*)(out + (size_t)idx4 * 4) = v;
}

// ---------------------------------------------------------------------------
// edge scatter: out[dst] += Y[src, 64 + etype*64 : +64]   (16 threads/edge)
// ---------------------------------------------------------------------------
__global__ void edge_scatter(const int* __restrict__ ei, const int* __restrict__ et,
                             int E, float* __restrict__ out) {
    int gid  = blockIdx.x * blockDim.x + threadIdx.x;
    int e    = gid >> 4;
    int lane = gid & 15;
    if (e >= E) return;
    int src = ei[e];
    int dst = ei[E + e];
    int ty  = et[e];
    const float4 v = *(const float4*)(g_Y + (size_t)src * NCOLS + DFEAT + ty * DFEAT + lane * 4);
    float* p = out + (size_t)dst * DFEAT + lane * 4;
    asm volatile("red.global.add.v4.f32 [%0], {%1, %2, %3, %4};"
                 :: "l"(p), "f"(v.x), "f"(v.y), "f"(v.z), "f"(v.w)
                 : "memory");
}

// ---------------------------------------------------------------------------
// relu in place
// ---------------------------------------------------------------------------
__global__ void relu_k(float* __restrict__ a, int total4) {
    int idx4 = blockIdx.x * blockDim.x + threadIdx.x;
    if (idx4 >= total4) return;
    float4 v = *(float4*)(a + (size_t)idx4 * 4);
    v.x = fmaxf(v.x, 0.0f); v.y = fmaxf(v.y, 0.0f);
    v.z = fmaxf(v.z, 0.0f); v.w = fmaxf(v.w, 0.0f);
    *(float4*)(a + (size_t)idx4 * 4) = v;
}

// ---------------------------------------------------------------------------
extern "C" void kernel_launch(void* const* d_in, const int* in_sizes, int n_in,
                              void* d_out, int out_size) {
    const float* x   = (const float*)d_in[0];
    const int*   ei  = (const int*)d_in[1];
    const int*   et  = (const int*)d_in[2];
    const float* W1  = (const float*)d_in[3];
    const float* sw1 = (const float*)d_in[4];
    const float* b1  = (const float*)d_in[5];
    const float* W2  = (const float*)d_in[6];
    const float* sw2 = (const float*)d_in[7];
    const float* b2  = (const float*)d_in[8];
    float* out = (float*)d_out;

    const int N = in_sizes[0] / DFEAT;
    const int E = in_sizes[2];
    const int total4 = N * (DFEAT / 4);

    float* hptr = nullptr;
    cudaGetSymbolAddress((void**)&hptr, g_h);

    dim3 gemm_grid((N + 127) / 128, NCOLS / 64);
    int pack_blocks = (DFEAT * NCOLS + 255) / 256;
    int ew_blocks   = (int)(((long long)E * 16 + 255) / 256);
    int el_blocks   = (total4 + 255) / 256;

    // ---- layer 1 (residual) ----
    pack_w<<<pack_blocks, 256>>>(W1, sw1);
    gemm_xw<<<gemm_grid, 128>>>(x, N);
    init_layer<<<el_blocks, 256>>>(x, b1, hptr, total4, 1);
    edge_scatter<<<ew_blocks, 256>>>(ei, et, E, hptr);
    relu_k<<<el_blocks, 256>>>(hptr, total4);

    // ---- layer 2 (no residual) ----
    pack_w<<<pack_blocks, 256>>>(W2, sw2);
    gemm_xw<<<gemm_grid, 128>>>(hptr, N);
    init_layer<<<el_blocks, 256>>>(x, b2, out, total4, 0);
    edge_scatter<<<ew_blocks, 256>>>(ei, et, E, out);
    relu_k<<<el_blocks, 256>>>(out, total4);
}

// round 3
// speedup vs baseline: 1.6315x; 1.6315x over previous
#include <cuda_runtime.h>
#include <cuda_bf16.h>
#include <cstdint>

#define DFEAT 64
#define NREL 16
#define NCOLS 1088   // (NREL+1)*64 : col 0..63 = self (sw), 64+r*64+j = W[r][:,j]
#define NNODE_MAX 100000

typedef unsigned long long u64;

// ---------------------------------------------------------------------------
// Scratch (allocation-free, __device__ globals)
// ---------------------------------------------------------------------------
__device__ float          g_Y[(size_t)NNODE_MAX * NCOLS];   // ~435 MB
__device__ float          g_h[(size_t)NNODE_MAX * DFEAT];   // layer-1 activations
__device__ __nv_bfloat16  g_Xhi[(size_t)NNODE_MAX * DFEAT];
__device__ __nv_bfloat16  g_Xlo[(size_t)NNODE_MAX * DFEAT];
__device__ __nv_bfloat16  g_Bhi[(size_t)NCOLS * DFEAT];     // B[c][k] = Wcat[k][c]
__device__ __nv_bfloat16  g_Blo[(size_t)NCOLS * DFEAT];

// ---------------------------------------------------------------------------
__device__ __forceinline__ uint32_t smem_to_u32(const void* p) {
    uint32_t a;
    asm("{ .reg .u64 t; cvta.to.shared.u64 t, %1; cvt.u32.u64 %0, t; }" : "=r"(a) : "l"(p));
    return a;
}
__device__ __forceinline__ void ldsm4(uint32_t* r, uint32_t a) {
    asm volatile("ldmatrix.sync.aligned.m8n8.x4.shared.b16 {%0,%1,%2,%3}, [%4];"
                 : "=r"(r[0]), "=r"(r[1]), "=r"(r[2]), "=r"(r[3]) : "r"(a));
}
__device__ __forceinline__ void mma_bf16(float* d, const uint32_t* a, const uint32_t* b) {
    asm volatile("mma.sync.aligned.m16n8k16.row.col.f32.bf16.bf16.f32 "
                 "{%0,%1,%2,%3}, {%4,%5,%6,%7}, {%8,%9}, {%0,%1,%2,%3};"
                 : "+f"(d[0]), "+f"(d[1]), "+f"(d[2]), "+f"(d[3])
                 : "r"(a[0]), "r"(a[1]), "r"(a[2]), "r"(a[3]), "r"(b[0]), "r"(b[1]));
}

// ---------------------------------------------------------------------------
// bf16 hi/lo conversion of activations
// ---------------------------------------------------------------------------
__global__ void conv_bf16(const float* __restrict__ src, int total4) {
    int idx4 = blockIdx.x * blockDim.x + threadIdx.x;
    if (idx4 >= total4) return;
    float4 v = *(const float4*)(src + (size_t)idx4 * 4);
    union { __nv_bfloat16 b[4]; uint2 u; } hi, lo;
    float f[4] = {v.x, v.y, v.z, v.w};
#pragma unroll
    for (int i = 0; i < 4; i++) {
        hi.b[i] = __float2bfloat16(f[i]);
        lo.b[i] = __float2bfloat16(f[i] - __bfloat162float(hi.b[i]));
    }
    *(uint2*)(g_Xhi + (size_t)idx4 * 4) = hi.u;
    *(uint2*)(g_Xlo + (size_t)idx4 * 4) = lo.u;
}

// ---------------------------------------------------------------------------
// Pack B[c][k] = Wcat[k][c] (bf16 hi/lo).  c<64 -> sw[k][c]; else W[r][k][j]
// ---------------------------------------------------------------------------
__global__ void pack_wb(const float* __restrict__ W, const float* __restrict__ sw) {
    int idx = blockIdx.x * blockDim.x + threadIdx.x;
    if (idx >= NCOLS * DFEAT) return;
    int c = idx / DFEAT;
    int k = idx - c * DFEAT;
    float v;
    if (c < DFEAT) {
        v = sw[k * DFEAT + c];
    } else {
        int rc = c - DFEAT;
        int r = rc >> 6, j = rc & 63;
        v = W[r * DFEAT * DFEAT + k * DFEAT + j];
    }
    __nv_bfloat16 hi = __float2bfloat16(v);
    __nv_bfloat16 lo = __float2bfloat16(v - __bfloat162float(hi));
    g_Bhi[idx] = hi;
    g_Blo[idx] = lo;
}

// ---------------------------------------------------------------------------
// GEMM via mma.sync bf16 split: tile 128 rows x 64 cols, 8 warps (4x2)
// col-tile 0 (self transform) fused with bias (+residual) -> outbuf
// other col-tiles -> g_Y
// ---------------------------------------------------------------------------
#define ASTRIDE 72                       // halves per A/B smem row (pad 64->72)
#define SM_AHI  0
#define SM_ALO  (128 * ASTRIDE * 2)      // 18432
#define SM_BHI  (SM_ALO + 128 * ASTRIDE * 2)
#define SM_BLO  (SM_BHI + 64 * ASTRIDE * 2)
#define SMEM_BYTES (SM_BLO + 64 * ASTRIDE * 2)   // 55296

__global__ void __launch_bounds__(256) gemm_mma(const float* __restrict__ xres,
                                                const float* __restrict__ bias,
                                                float* __restrict__ outbuf,
                                                int N, int residual) {
    extern __shared__ char smem[];
    const uint32_t sb = smem_to_u32(smem);
    const int t   = threadIdx.x;
    const int wid = t >> 5, lid = t & 31;
    const int n0  = blockIdx.x * 128;
    const int ct  = blockIdx.y;          // col tile (64 cols): 0=self, 1..16=relations
    const int cg0 = ct * 64;

    // ---- load A tiles (128 rows x 64 halves each) ----
    const uint4* XhiV = (const uint4*)g_Xhi;
    const uint4* XloV = (const uint4*)g_Xlo;
#pragma unroll
    for (int i = t; i < 1024; i += 256) {
        int row = i >> 3, q = i & 7;
        int n = n0 + row; if (n >= N) n = N - 1;
        uint32_t d = (uint32_t)(row * ASTRIDE * 2 + q * 16);
        *(uint4*)(smem + SM_AHI + d) = XhiV[(size_t)n * 8 + q];
        *(uint4*)(smem + SM_ALO + d) = XloV[(size_t)n * 8 + q];
    }
    // ---- load B tiles (64 cols x 64 halves each) ----
    const uint4* BhiV = (const uint4*)g_Bhi;
    const uint4* BloV = (const uint4*)g_Blo;
#pragma unroll
    for (int i = t; i < 512; i += 256) {
        int row = i >> 3, q = i & 7;
        uint32_t d = (uint32_t)(row * ASTRIDE * 2 + q * 16);
        *(uint4*)(smem + SM_BHI + d) = BhiV[(size_t)(cg0 + row) * 8 + q];
        *(uint4*)(smem + SM_BLO + d) = BloV[(size_t)(cg0 + row) * 8 + q];
    }
    __syncthreads();

    const int wr = wid >> 1;     // warp row 0..3  -> rows wr*32..+31
    const int wc = wid & 1;      // warp col 0..1  -> cols wc*32..+31
    const int sub = lid >> 3;    // ldmatrix sub-matrix id
    const int l7  = lid & 7;

    float acc[2][4][4];
#pragma unroll
    for (int mi = 0; mi < 2; mi++)
#pragma unroll
        for (int nt = 0; nt < 4; nt++)
#pragma unroll
            for (int q = 0; q < 4; q++) acc[mi][nt][q] = 0.0f;

    // A ldmatrix lane address pieces: matrices (m0k0, m8k0, m0k8, m8k8)
    const int a_row = wr * 32 + ((sub & 1) << 3) + l7;
    const int a_kof = (sub >> 1) << 3;
    // B ldmatrix: matrices (n0k0, n0k8, n8k0, n8k8)
    const int b_row = wc * 32 + ((sub >> 1) << 3) + l7;
    const int b_kof = (sub & 1) << 3;

#pragma unroll
    for (int ks = 0; ks < 4; ks++) {
        const int k0 = ks * 16;
        uint32_t ah[2][4], al[2][4], bh[2][4], bl[2][4];
#pragma unroll
        for (int mi = 0; mi < 2; mi++) {
            uint32_t off = (uint32_t)((a_row + mi * 16) * ASTRIDE + k0 + a_kof) * 2;
            ldsm4(ah[mi], sb + SM_AHI + off);
            ldsm4(al[mi], sb + SM_ALO + off);
        }
#pragma unroll
        for (int nj = 0; nj < 2; nj++) {
            uint32_t off = (uint32_t)((b_row + nj * 16) * ASTRIDE + k0 + b_kof) * 2;
            ldsm4(bh[nj], sb + SM_BHI + off);
            ldsm4(bl[nj], sb + SM_BLO + off);
        }
#pragma unroll
        for (int mi = 0; mi < 2; mi++)
#pragma unroll
            for (int nt = 0; nt < 4; nt++) {
                const uint32_t* bhp = &bh[nt >> 1][(nt & 1) * 2];
                const uint32_t* blp = &bl[nt >> 1][(nt & 1) * 2];
                mma_bf16(acc[mi][nt], ah[mi], bhp);
                mma_bf16(acc[mi][nt], ah[mi], blp);
                mma_bf16(acc[mi][nt], al[mi], bhp);
            }
    }

    // ---- epilogue ----
    const int g  = lid >> 2;     // 0..7
    const int tg = lid & 3;      // 0..3
#pragma unroll
    for (int mi = 0; mi < 2; mi++) {
#pragma unroll
        for (int hf = 0; hf < 2; hf++) {
            int row = n0 + wr * 32 + mi * 16 + g + hf * 8;
            if (row >= N) continue;
#pragma unroll
            for (int nt = 0; nt < 4; nt++) {
                int cl = wc * 32 + nt * 8 + tg * 2;   // local col 0..63
                float v0 = acc[mi][nt][hf * 2 + 0];
                float v1 = acc[mi][nt][hf * 2 + 1];
                if (ct == 0) {
                    v0 += bias[cl];
                    v1 += bias[cl + 1];
                    if (residual) {
                        v0 += xres[(size_t)row * DFEAT + cl];
                        v1 += xres[(size_t)row * DFEAT + cl + 1];
                    }
                    *(float2*)(outbuf + (size_t)row * DFEAT + cl) = make_float2(v0, v1);
                } else {
                    *(float2*)(g_Y + (size_t)row * NCOLS + cg0 + cl) = make_float2(v0, v1);
                }
            }
        }
    }
}

// ---------------------------------------------------------------------------
// edge scatter: out[dst] += Y[src, etype-tile]   (16 threads/edge)
// ---------------------------------------------------------------------------
__global__ void edge_scatter(const int* __restrict__ ei, const int* __restrict__ et,
                             int E, float* __restrict__ out) {
    int gid  = blockIdx.x * blockDim.x + threadIdx.x;
    int e    = gid >> 4;
    int lane = gid & 15;
    if (e >= E) return;
    int src = ei[e];
    int dst = ei[E + e];
    int ty  = et[e];
    const float4 v = *(const float4*)(g_Y + (size_t)src * NCOLS + DFEAT + ty * DFEAT + lane * 4);
    float* p = out + (size_t)dst * DFEAT + lane * 4;
    asm volatile("red.global.add.v4.f32 [%0], {%1, %2, %3, %4};"
                 :: "l"(p), "f"(v.x), "f"(v.y), "f"(v.z), "f"(v.w)
                 : "memory");
}

// ---------------------------------------------------------------------------
__global__ void relu_k(float* __restrict__ a, int total4) {
    int idx4 = blockIdx.x * blockDim.x + threadIdx.x;
    if (idx4 >= total4) return;
    float4 v = *(float4*)(a + (size_t)idx4 * 4);
    v.x = fmaxf(v.x, 0.0f); v.y = fmaxf(v.y, 0.0f);
    v.z = fmaxf(v.z, 0.0f); v.w = fmaxf(v.w, 0.0f);
    *(float4*)(a + (size_t)idx4 * 4) = v;
}

// ---------------------------------------------------------------------------
extern "C" void kernel_launch(void* const* d_in, const int* in_sizes, int n_in,
                              void* d_out, int out_size) {
    const float* x   = (const float*)d_in[0];
    const int*   ei  = (const int*)d_in[1];
    const int*   et  = (const int*)d_in[2];
    const float* W1  = (const float*)d_in[3];
    const float* sw1 = (const float*)d_in[4];
    const float* b1  = (const float*)d_in[5];
    const float* W2  = (const float*)d_in[6];
    const float* sw2 = (const float*)d_in[7];
    const float* b2  = (const float*)d_in[8];
    float* out = (float*)d_out;

    const int N = in_sizes[0] / DFEAT;
    const int E = in_sizes[2];
    const int total4 = N * (DFEAT / 4);

    float* hptr = nullptr;
    cudaGetSymbolAddress((void**)&hptr, g_h);

    cudaFuncSetAttribute(gemm_mma, cudaFuncAttributeMaxDynamicSharedMemorySize, SMEM_BYTES);

    dim3 gemm_grid((N + 127) / 128, NCOLS / 64);
    int pack_blocks = (NCOLS * DFEAT + 255) / 256;
    int ew_blocks   = (int)(((long long)E * 16 + 255) / 256);
    int el_blocks   = (total4 + 255) / 256;

    // ---- layer 1 (residual) ----
    conv_bf16<<<el_blocks, 256>>>(x, total4);
    pack_wb<<<pack_blocks, 256>>>(W1, sw1);
    gemm_mma<<<gemm_grid, 256, SMEM_BYTES>>>(x, b1, hptr, N, 1);
    edge_scatter<<<ew_blocks, 256>>>(ei, et, E, hptr);
    relu_k<<<el_blocks, 256>>>(hptr, total4);

    // ---- layer 2 (no residual) ----
    conv_bf16<<<el_blocks, 256>>>(hptr, total4);
    pack_wb<<<pack_blocks, 256>>>(W2, sw2);
    gemm_mma<<<gemm_grid, 256, SMEM_BYTES>>>(x, b2, out, N, 0);
    edge_scatter<<<ew_blocks, 256>>>(ei, et, E, out);
    relu_k<<<el_blocks, 256>>>(out, total4);
}

// round 4
// speedup vs baseline: 1.9038x; 1.1669x over previous
#include <cuda_runtime.h>
#include <cuda_bf16.h>
#include <cuda_fp16.h>
#include <cstdint>

#define DFEAT 64
#define NREL 16
#define NCOLS 1088           // (NREL+1)*64
#define RELCOLS 1024         // NREL*64 halves per Yh row
#define NNODE_MAX 100000
#define EDGE_MAX  1500000
#define NBLK_MAX  128        // ceil(NNODE_MAX/1024) = 98

typedef unsigned long long u64;

// ---------------------------------------------------------------------------
// Scratch (allocation-free, __device__ globals)
// ---------------------------------------------------------------------------
__device__ __half         g_Yh[(size_t)NNODE_MAX * RELCOLS];  // ~205 MB fp16 messages
__device__ float          g_h[(size_t)NNODE_MAX * DFEAT];
__device__ __nv_bfloat16  g_Xhi[(size_t)NNODE_MAX * DFEAT];
__device__ __nv_bfloat16  g_Xlo[(size_t)NNODE_MAX * DFEAT];
__device__ __nv_bfloat16  g_Bhi[(size_t)NCOLS * DFEAT];
__device__ __nv_bfloat16  g_Blo[(size_t)NCOLS * DFEAT];
// CSR
__device__ int      g_cnt[NNODE_MAX];
__device__ int      g_indptr[NNODE_MAX + 1];
__device__ int      g_cursor[NNODE_MAX];
__device__ int      g_bsum[NBLK_MAX];
__device__ uint32_t g_edata[EDGE_MAX];   // src | ty<<20

// ---------------------------------------------------------------------------
__device__ __forceinline__ uint32_t smem_to_u32(const void* p) {
    uint32_t a;
    asm("{ .reg .u64 t; cvta.to.shared.u64 t, %1; cvt.u32.u64 %0, t; }" : "=r"(a) : "l"(p));
    return a;
}
__device__ __forceinline__ void ldsm4(uint32_t* r, uint32_t a) {
    asm volatile("ldmatrix.sync.aligned.m8n8.x4.shared.b16 {%0,%1,%2,%3}, [%4];"
                 : "=r"(r[0]), "=r"(r[1]), "=r"(r[2]), "=r"(r[3]) : "r"(a));
}
__device__ __forceinline__ void mma_bf16(float* d, const uint32_t* a, const uint32_t* b) {
    asm volatile("mma.sync.aligned.m16n8k16.row.col.f32.bf16.bf16.f32 "
                 "{%0,%1,%2,%3}, {%4,%5,%6,%7}, {%8,%9}, {%0,%1,%2,%3};"
                 : "+f"(d[0]), "+f"(d[1]), "+f"(d[2]), "+f"(d[3])
                 : "r"(a[0]), "r"(a[1]), "r"(a[2]), "r"(a[3]), "r"(b[0]), "r"(b[1]));
}

// ---------------------------------------------------------------------------
// CSR build kernels
// ---------------------------------------------------------------------------
__global__ void zero_cnt(int N) {
    int i = blockIdx.x * blockDim.x + threadIdx.x;
    if (i < N) g_cnt[i] = 0;
}
__global__ void hist_k(const int* __restrict__ ei, int E) {
    int e = blockIdx.x * blockDim.x + threadIdx.x;
    if (e >= E) return;
    atomicAdd(&g_cnt[ei[E + e]], 1);
}
__global__ void scan1(int N) {   // block-level exclusive scan of g_cnt -> g_indptr
    __shared__ int sh[1024];
    int gid = blockIdx.x * 1024 + threadIdx.x;
    int v = (gid < N) ? g_cnt[gid] : 0;
    sh[threadIdx.x] = v;
    __syncthreads();
    for (int off = 1; off < 1024; off <<= 1) {
        int t = (threadIdx.x >= off) ? sh[threadIdx.x - off] : 0;
        __syncthreads();
        sh[threadIdx.x] += t;
        __syncthreads();
    }
    if (gid < N) g_indptr[gid] = sh[threadIdx.x] - v;       // exclusive within block
    if (threadIdx.x == 1023) g_bsum[blockIdx.x] = sh[1023]; // block total
}
__global__ void scan2(int nb) {  // exclusive scan of block sums (single block)
    __shared__ int sh[NBLK_MAX];
    int t = threadIdx.x;
    int v = (t < nb) ? g_bsum[t] : 0;
    sh[t] = v;
    __syncthreads();
    for (int off = 1; off < NBLK_MAX; off <<= 1) {
        int a = (t >= off) ? sh[t - off] : 0;
        __syncthreads();
        sh[t] += a;
        __syncthreads();
    }
    if (t < nb) g_bsum[t] = sh[t] - v;
}
__global__ void scan3(int N, int E) {
    int gid = blockIdx.x * 1024 + threadIdx.x;
    if (gid < N) {
        int v = g_indptr[gid] + g_bsum[blockIdx.x];
        g_indptr[gid] = v;
        g_cursor[gid] = v;
    }
    if (gid == 0) g_indptr[N] = E;
}
__global__ void fill_k(const int* __restrict__ ei, const int* __restrict__ et, int E) {
    int e = blockIdx.x * blockDim.x + threadIdx.x;
    if (e >= E) return;
    int src = ei[e];
    int dst = ei[E + e];
    int ty  = et[e];
    int pos = atomicAdd(&g_cursor[dst], 1);
    g_edata[pos] = (uint32_t)src | ((uint32_t)ty << 20);
}

// ---------------------------------------------------------------------------
// bf16 hi/lo conversion of activations (optional fused relu)
// ---------------------------------------------------------------------------
__global__ void conv_bf16(const float* __restrict__ src, int total4, int relu) {
    int idx4 = blockIdx.x * blockDim.x + threadIdx.x;
    if (idx4 >= total4) return;
    float4 v = *(const float4*)(src + (size_t)idx4 * 4);
    float f[4] = {v.x, v.y, v.z, v.w};
    union { __nv_bfloat16 b[4]; uint2 u; } hi, lo;
#pragma unroll
    for (int i = 0; i < 4; i++) {
        if (relu) f[i] = fmaxf(f[i], 0.0f);
        hi.b[i] = __float2bfloat16(f[i]);
        lo.b[i] = __float2bfloat16(f[i] - __bfloat162float(hi.b[i]));
    }
    *(uint2*)(g_Xhi + (size_t)idx4 * 4) = hi.u;
    *(uint2*)(g_Xlo + (size_t)idx4 * 4) = lo.u;
}

// ---------------------------------------------------------------------------
// Pack B[c][k] = Wcat[k][c] (bf16 hi/lo)
// ---------------------------------------------------------------------------
__global__ void pack_wb(const float* __restrict__ W, const float* __restrict__ sw) {
    int idx = blockIdx.x * blockDim.x + threadIdx.x;
    if (idx >= NCOLS * DFEAT) return;
    int c = idx / DFEAT;
    int k = idx - c * DFEAT;
    float v;
    if (c < DFEAT) {
        v = sw[k * DFEAT + c];
    } else {
        int rc = c - DFEAT;
        int r = rc >> 6, j = rc & 63;
        v = W[r * DFEAT * DFEAT + k * DFEAT + j];
    }
    __nv_bfloat16 hi = __float2bfloat16(v);
    __nv_bfloat16 lo = __float2bfloat16(v - __bfloat162float(hi));
    g_Bhi[idx] = hi;
    g_Blo[idx] = lo;
}

// ---------------------------------------------------------------------------
// GEMM via mma.sync bf16 split: 128x64 tile, 8 warps.
// ct==0: self transform + bias (+residual) -> outbuf (fp32)
// ct>=1: relation messages -> g_Yh (fp16)
// ---------------------------------------------------------------------------
#define ASTRIDE 72
#define SM_AHI  0
#define SM_ALO  (128 * ASTRIDE * 2)
#define SM_BHI  (SM_ALO + 128 * ASTRIDE * 2)
#define SM_BLO  (SM_BHI + 64 * ASTRIDE * 2)
#define SMEM_BYTES (SM_BLO + 64 * ASTRIDE * 2)   // 55296

__global__ void __launch_bounds__(256) gemm_mma(const float* __restrict__ xres,
                                                const float* __restrict__ bias,
                                                float* __restrict__ outbuf,
                                                int N, int residual) {
    extern __shared__ char smem[];
    const uint32_t sb = smem_to_u32(smem);
    const int t   = threadIdx.x;
    const int wid = t >> 5, lid = t & 31;
    const int n0  = blockIdx.x * 128;
    const int ct  = blockIdx.y;
    const int cg0 = ct * 64;

    const uint4* XhiV = (const uint4*)g_Xhi;
    const uint4* XloV = (const uint4*)g_Xlo;
#pragma unroll
    for (int i = t; i < 1024; i += 256) {
        int row = i >> 3, q = i & 7;
        int n = n0 + row; if (n >= N) n = N - 1;
        uint32_t d = (uint32_t)(row * ASTRIDE * 2 + q * 16);
        *(uint4*)(smem + SM_AHI + d) = XhiV[(size_t)n * 8 + q];
        *(uint4*)(smem + SM_ALO + d) = XloV[(size_t)n * 8 + q];
    }
    const uint4* BhiV = (const uint4*)g_Bhi;
    const uint4* BloV = (const uint4*)g_Blo;
#pragma unroll
    for (int i = t; i < 512; i += 256) {
        int row = i >> 3, q = i & 7;
        uint32_t d = (uint32_t)(row * ASTRIDE * 2 + q * 16);
        *(uint4*)(smem + SM_BHI + d) = BhiV[(size_t)(cg0 + row) * 8 + q];
        *(uint4*)(smem + SM_BLO + d) = BloV[(size_t)(cg0 + row) * 8 + q];
    }
    __syncthreads();

    const int wr = wid >> 1;
    const int wc = wid & 1;
    const int sub = lid >> 3;
    const int l7  = lid & 7;

    float acc[2][4][4];
#pragma unroll
    for (int mi = 0; mi < 2; mi++)
#pragma unroll
        for (int nt = 0; nt < 4; nt++)
#pragma unroll
            for (int q = 0; q < 4; q++) acc[mi][nt][q] = 0.0f;

    const int a_row = wr * 32 + ((sub & 1) << 3) + l7;
    const int a_kof = (sub >> 1) << 3;
    const int b_row = wc * 32 + ((sub >> 1) << 3) + l7;
    const int b_kof = (sub & 1) << 3;

#pragma unroll
    for (int ks = 0; ks < 4; ks++) {
        const int k0 = ks * 16;
        uint32_t ah[2][4], al[2][4], bh[2][4], bl[2][4];
#pragma unroll
        for (int mi = 0; mi < 2; mi++) {
            uint32_t off = (uint32_t)((a_row + mi * 16) * ASTRIDE + k0 + a_kof) * 2;
            ldsm4(ah[mi], sb + SM_AHI + off);
            ldsm4(al[mi], sb + SM_ALO + off);
        }
#pragma unroll
        for (int nj = 0; nj < 2; nj++) {
            uint32_t off = (uint32_t)((b_row + nj * 16) * ASTRIDE + k0 + b_kof) * 2;
            ldsm4(bh[nj], sb + SM_BHI + off);
            ldsm4(bl[nj], sb + SM_BLO + off);
        }
#pragma unroll
        for (int mi = 0; mi < 2; mi++)
#pragma unroll
            for (int nt = 0; nt < 4; nt++) {
                const uint32_t* bhp = &bh[nt >> 1][(nt & 1) * 2];
                const uint32_t* blp = &bl[nt >> 1][(nt & 1) * 2];
                mma_bf16(acc[mi][nt], ah[mi], bhp);
                mma_bf16(acc[mi][nt], ah[mi], blp);
                mma_bf16(acc[mi][nt], al[mi], bhp);
            }
    }

    const int g  = lid >> 2;
    const int tg = lid & 3;
#pragma unroll
    for (int mi = 0; mi < 2; mi++) {
#pragma unroll
        for (int hf = 0; hf < 2; hf++) {
            int row = n0 + wr * 32 + mi * 16 + g + hf * 8;
            if (row >= N) continue;
#pragma unroll
            for (int nt = 0; nt < 4; nt++) {
                int cl = wc * 32 + nt * 8 + tg * 2;
                float v0 = acc[mi][nt][hf * 2 + 0];
                float v1 = acc[mi][nt][hf * 2 + 1];
                if (ct == 0) {
                    v0 += bias[cl];
                    v1 += bias[cl + 1];
                    if (residual) {
                        v0 += xres[(size_t)row * DFEAT + cl];
                        v1 += xres[(size_t)row * DFEAT + cl + 1];
                    }
                    *(float2*)(outbuf + (size_t)row * DFEAT + cl) = make_float2(v0, v1);
                } else {
                    __half2 hv = __floats2half2_rn(v0, v1);
                    *(__half2*)(g_Yh + (size_t)row * RELCOLS + (cg0 - DFEAT) + cl) = hv;
                }
            }
        }
    }
}

// ---------------------------------------------------------------------------
// CSR aggregation: one warp per dst node. inout[node] += sum(msgs); optional relu
// ---------------------------------------------------------------------------
__global__ void __launch_bounds__(256) agg_k(float* __restrict__ inout, int N, int relu) {
    const int wid  = threadIdx.x >> 5;
    const int lid  = threadIdx.x & 31;
    const int node = blockIdx.x * 8 + wid;
    if (node >= N) return;

    const int s  = g_indptr[node];
    const int e2 = g_indptr[node + 1];

    float ax = 0.0f, ay = 0.0f;
    const __half* Yh = g_Yh;

    int i = s;
    for (; i + 1 < e2; i += 2) {
        uint32_t p0 = g_edata[i];
        uint32_t p1 = g_edata[i + 1];
        const __half2 v0 = *(const __half2*)(Yh + (size_t)(p0 & 0xFFFFF) * RELCOLS
                                             + ((p0 >> 20) << 6) + lid * 2);
        const __half2 v1 = *(const __half2*)(Yh + (size_t)(p1 & 0xFFFFF) * RELCOLS
                                             + ((p1 >> 20) << 6) + lid * 2);
        float2 f0 = __half22float2(v0);
        float2 f1 = __half22float2(v1);
        ax += f0.x + f1.x;
        ay += f0.y + f1.y;
    }
    if (i < e2) {
        uint32_t p0 = g_edata[i];
        const __half2 v0 = *(const __half2*)(Yh + (size_t)(p0 & 0xFFFFF) * RELCOLS
                                             + ((p0 >> 20) << 6) + lid * 2);
        float2 f0 = __half22float2(v0);
        ax += f0.x;
        ay += f0.y;
    }

    float* p = inout + (size_t)node * DFEAT + lid * 2;
    float2 base = *(float2*)p;
    float rx = base.x + ax;
    float ry = base.y + ay;
    if (relu) { rx = fmaxf(rx, 0.0f); ry = fmaxf(ry, 0.0f); }
    *(float2*)p = make_float2(rx, ry);
}

// ---------------------------------------------------------------------------
extern "C" void kernel_launch(void* const* d_in, const int* in_sizes, int n_in,
                              void* d_out, int out_size) {
    const float* x   = (const float*)d_in[0];
    const int*   ei  = (const int*)d_in[1];
    const int*   et  = (const int*)d_in[2];
    const float* W1  = (const float*)d_in[3];
    const float* sw1 = (const float*)d_in[4];
    const float* b1  = (const float*)d_in[5];
    const float* W2  = (const float*)d_in[6];
    const float* sw2 = (const float*)d_in[7];
    const float* b2  = (const float*)d_in[8];
    float* out = (float*)d_out;

    const int N = in_sizes[0] / DFEAT;
    const int E = in_sizes[2];
    const int total4 = N * (DFEAT / 4);
    const int nb = (N + 1023) / 1024;

    float* hptr = nullptr;
    cudaGetSymbolAddress((void**)&hptr, g_h);

    cudaFuncSetAttribute(gemm_mma, cudaFuncAttributeMaxDynamicSharedMemorySize, SMEM_BYTES);

    dim3 gemm_grid((N + 127) / 128, NCOLS / 64);
    int pack_blocks = (NCOLS * DFEAT + 255) / 256;
    int el_blocks   = (total4 + 255) / 256;
    int e_blocks    = (E + 255) / 256;
    int n_blocks    = (N + 255) / 256;
    int agg_blocks  = (N + 7) / 8;

    // ---- CSR build (once per launch, reused by both layers) ----
    zero_cnt<<<n_blocks, 256>>>(N);
    hist_k<<<e_blocks, 256>>>(ei, E);
    scan1<<<nb, 1024>>>(N);
    scan2<<<1, NBLK_MAX>>>(nb);
    scan3<<<nb, 1024>>>(N, E);
    fill_k<<<e_blocks, 256>>>(ei, et, E);

    // ---- layer 1 (residual) ----
    conv_bf16<<<el_blocks, 256>>>(x, total4, 0);
    pack_wb<<<pack_blocks, 256>>>(W1, sw1);
    gemm_mma<<<gemm_grid, 256, SMEM_BYTES>>>(x, b1, hptr, N, 1);
    agg_k<<<agg_blocks, 256>>>(hptr, N, 0);

    // ---- layer 2 (no residual; relu of layer 1 fused into conv) ----
    conv_bf16<<<el_blocks, 256>>>(hptr, total4, 1);
    pack_wb<<<pack_blocks, 256>>>(W2, sw2);
    gemm_mma<<<gemm_grid, 256, SMEM_BYTES>>>(x, b2, out, N, 0);
    agg_k<<<agg_blocks, 256>>>(out, N, 1);
}

// round 5
// speedup vs baseline: 2.0744x; 1.0896x over previous
#include <cuda_runtime.h>
#include <cuda_fp16.h>
#include <cstdint>

#define DFEAT 64
#define NREL 16
#define NCOLS 1088           // (NREL+1)*64
#define RELCOLS 1024         // NREL*64 halves per Yh row
#define NNODE_MAX 100000
#define EDGE_MAX  1500000
#define NBLK_MAX  128

typedef unsigned long long u64;

// ---------------------------------------------------------------------------
// Scratch (allocation-free, __device__ globals)
// ---------------------------------------------------------------------------
__device__ __half  g_Yh[(size_t)NNODE_MAX * RELCOLS];  // ~205 MB fp16 messages
__device__ float   g_h[(size_t)NNODE_MAX * DFEAT];
__device__ __half  g_Xhi[(size_t)NNODE_MAX * DFEAT];
__device__ __half  g_Xlo[(size_t)NNODE_MAX * DFEAT];
__device__ __half  g_Bhi[(size_t)NCOLS * DFEAT];
__device__ __half  g_Blo[(size_t)NCOLS * DFEAT];
// CSR
__device__ int      g_cnt[NNODE_MAX];
__device__ int      g_indptr[NNODE_MAX + 1];
__device__ int      g_cursor[NNODE_MAX];
__device__ int      g_bsum[NBLK_MAX];
__device__ uint32_t g_edata[EDGE_MAX];   // src | ty<<20

// ---------------------------------------------------------------------------
__device__ __forceinline__ uint32_t smem_to_u32(const void* p) {
    uint32_t a;
    asm("{ .reg .u64 t; cvta.to.shared.u64 t, %1; cvt.u32.u64 %0, t; }" : "=r"(a) : "l"(p));
    return a;
}
__device__ __forceinline__ void ldsm4(uint32_t* r, uint32_t a) {
    asm volatile("ldmatrix.sync.aligned.m8n8.x4.shared.b16 {%0,%1,%2,%3}, [%4];"
                 : "=r"(r[0]), "=r"(r[1]), "=r"(r[2]), "=r"(r[3]) : "r"(a));
}
__device__ __forceinline__ void mma_fp16(float* d, const uint32_t* a, const uint32_t* b) {
    asm volatile("mma.sync.aligned.m16n8k16.row.col.f32.f16.f16.f32 "
                 "{%0,%1,%2,%3}, {%4,%5,%6,%7}, {%8,%9}, {%0,%1,%2,%3};"
                 : "+f"(d[0]), "+f"(d[1]), "+f"(d[2]), "+f"(d[3])
                 : "r"(a[0]), "r"(a[1]), "r"(a[2]), "r"(a[3]), "r"(b[0]), "r"(b[1]));
}

// ---------------------------------------------------------------------------
// CSR build kernels
// ---------------------------------------------------------------------------
__global__ void zero_cnt(int N) {
    int i = blockIdx.x * blockDim.x + threadIdx.x;
    if (i < N) g_cnt[i] = 0;
}
__global__ void hist_k(const int* __restrict__ ei, int E) {
    int e = blockIdx.x * blockDim.x + threadIdx.x;
    if (e >= E) return;
    atomicAdd(&g_cnt[ei[E + e]], 1);
}
__global__ void scan1(int N) {
    __shared__ int sh[1024];
    int gid = blockIdx.x * 1024 + threadIdx.x;
    int v = (gid < N) ? g_cnt[gid] : 0;
    sh[threadIdx.x] = v;
    __syncthreads();
    for (int off = 1; off < 1024; off <<= 1) {
        int t = (threadIdx.x >= off) ? sh[threadIdx.x - off] : 0;
        __syncthreads();
        sh[threadIdx.x] += t;
        __syncthreads();
    }
    if (gid < N) g_indptr[gid] = sh[threadIdx.x] - v;
    if (threadIdx.x == 1023) g_bsum[blockIdx.x] = sh[1023];
}
__global__ void scan2(int nb) {
    __shared__ int sh[NBLK_MAX];
    int t = threadIdx.x;
    int v = (t < nb) ? g_bsum[t] : 0;
    sh[t] = v;
    __syncthreads();
    for (int off = 1; off < NBLK_MAX; off <<= 1) {
        int a = (t >= off) ? sh[t - off] : 0;
        __syncthreads();
        sh[t] += a;
        __syncthreads();
    }
    if (t < nb) g_bsum[t] = sh[t] - v;
}
__global__ void scan3(int N, int E) {
    int gid = blockIdx.x * 1024 + threadIdx.x;
    if (gid < N) {
        int v = g_indptr[gid] + g_bsum[blockIdx.x];
        g_indptr[gid] = v;
        g_cursor[gid] = v;
    }
    if (gid == 0) g_indptr[N] = E;
}
__global__ void fill_k(const int* __restrict__ ei, const int* __restrict__ et, int E) {
    int e = blockIdx.x * blockDim.x + threadIdx.x;
    if (e >= E) return;
    int src = ei[e];
    int dst = ei[E + e];
    int ty  = et[e];
    int pos = atomicAdd(&g_cursor[dst], 1);
    g_edata[pos] = (uint32_t)src | ((uint32_t)ty << 20);
}

// ---------------------------------------------------------------------------
// fp16 hi/lo conversion of activations (optional fused relu)
// ---------------------------------------------------------------------------
__global__ void conv_fp16(const float* __restrict__ src, int total4, int relu) {
    int idx4 = blockIdx.x * blockDim.x + threadIdx.x;
    if (idx4 >= total4) return;
    float4 v = *(const float4*)(src + (size_t)idx4 * 4);
    float f[4] = {v.x, v.y, v.z, v.w};
    union { __half b[4]; uint2 u; } hi, lo;
#pragma unroll
    for (int i = 0; i < 4; i++) {
        if (relu) f[i] = fmaxf(f[i], 0.0f);
        hi.b[i] = __float2half_rn(f[i]);
        lo.b[i] = __float2half_rn(f[i] - __half2float(hi.b[i]));
    }
    *(uint2*)(g_Xhi + (size_t)idx4 * 4) = hi.u;
    *(uint2*)(g_Xlo + (size_t)idx4 * 4) = lo.u;
}

// ---------------------------------------------------------------------------
// Pack B[c][k] = Wcat[k][c] (fp16 hi/lo)
// ---------------------------------------------------------------------------
__global__ void pack_wb(const float* __restrict__ W, const float* __restrict__ sw) {
    int idx = blockIdx.x * blockDim.x + threadIdx.x;
    if (idx >= NCOLS * DFEAT) return;
    int c = idx / DFEAT;
    int k = idx - c * DFEAT;
    float v;
    if (c < DFEAT) {
        v = sw[k * DFEAT + c];
    } else {
        int rc = c - DFEAT;
        int r = rc >> 6, j = rc & 63;
        v = W[r * DFEAT * DFEAT + k * DFEAT + j];
    }
    __half hi = __float2half_rn(v);
    __half lo = __float2half_rn(v - __half2float(hi));
    g_Bhi[idx] = hi;
    g_Blo[idx] = lo;
}

// ---------------------------------------------------------------------------
// GEMM via mma.sync fp16 split: 128x64 tile, 8 warps.
// ct==0: 3-term, self transform + bias (+residual) -> outbuf (fp32)
// ct>=1: 2-term (Ahi*Bhi + Ahi*Blo), messages -> g_Yh (fp16)
// ---------------------------------------------------------------------------
#define ASTRIDE 72
#define SM_AHI  0
#define SM_ALO  (128 * ASTRIDE * 2)
#define SM_BHI  (SM_ALO + 128 * ASTRIDE * 2)
#define SM_BLO  (SM_BHI + 64 * ASTRIDE * 2)
#define SMEM_BYTES (SM_BLO + 64 * ASTRIDE * 2)   // 55296

__global__ void __launch_bounds__(256) gemm_mma(const float* __restrict__ xres,
                                                const float* __restrict__ bias,
                                                float* __restrict__ outbuf,
                                                int N, int residual) {
    extern __shared__ char smem[];
    const uint32_t sb = smem_to_u32(smem);
    const int t   = threadIdx.x;
    const int wid = t >> 5, lid = t & 31;
    const int n0  = blockIdx.x * 128;
    const int ct  = blockIdx.y;
    const int cg0 = ct * 64;
    const bool self_tile = (ct == 0);

    const uint4* XhiV = (const uint4*)g_Xhi;
    const uint4* XloV = (const uint4*)g_Xlo;
#pragma unroll
    for (int i = t; i < 1024; i += 256) {
        int row = i >> 3, q = i & 7;
        int n = n0 + row; if (n >= N) n = N - 1;
        uint32_t d = (uint32_t)(row * ASTRIDE * 2 + q * 16);
        *(uint4*)(smem + SM_AHI + d) = XhiV[(size_t)n * 8 + q];
        if (self_tile)
            *(uint4*)(smem + SM_ALO + d) = XloV[(size_t)n * 8 + q];
    }
    const uint4* BhiV = (const uint4*)g_Bhi;
    const uint4* BloV = (const uint4*)g_Blo;
#pragma unroll
    for (int i = t; i < 512; i += 256) {
        int row = i >> 3, q = i & 7;
        uint32_t d = (uint32_t)(row * ASTRIDE * 2 + q * 16);
        *(uint4*)(smem + SM_BHI + d) = BhiV[(size_t)(cg0 + row) * 8 + q];
        *(uint4*)(smem + SM_BLO + d) = BloV[(size_t)(cg0 + row) * 8 + q];
    }
    __syncthreads();

    const int wr = wid >> 1;
    const int wc = wid & 1;
    const int sub = lid >> 3;
    const int l7  = lid & 7;

    float acc[2][4][4];
#pragma unroll
    for (int mi = 0; mi < 2; mi++)
#pragma unroll
        for (int nt = 0; nt < 4; nt++)
#pragma unroll
            for (int q = 0; q < 4; q++) acc[mi][nt][q] = 0.0f;

    const int a_row = wr * 32 + ((sub & 1) << 3) + l7;
    const int a_kof = (sub >> 1) << 3;
    const int b_row = wc * 32 + ((sub >> 1) << 3) + l7;
    const int b_kof = (sub & 1) << 3;

#pragma unroll
    for (int ks = 0; ks < 4; ks++) {
        const int k0 = ks * 16;
        uint32_t ah[2][4], bh[2][4], bl[2][4];
#pragma unroll
        for (int mi = 0; mi < 2; mi++) {
            uint32_t off = (uint32_t)((a_row + mi * 16) * ASTRIDE + k0 + a_kof) * 2;
            ldsm4(ah[mi], sb + SM_AHI + off);
        }
#pragma unroll
        for (int nj = 0; nj < 2; nj++) {
            uint32_t off = (uint32_t)((b_row + nj * 16) * ASTRIDE + k0 + b_kof) * 2;
            ldsm4(bh[nj], sb + SM_BHI + off);
            ldsm4(bl[nj], sb + SM_BLO + off);
        }
#pragma unroll
        for (int mi = 0; mi < 2; mi++)
#pragma unroll
            for (int nt = 0; nt < 4; nt++) {
                const uint32_t* bhp = &bh[nt >> 1][(nt & 1) * 2];
                const uint32_t* blp = &bl[nt >> 1][(nt & 1) * 2];
                mma_fp16(acc[mi][nt], ah[mi], bhp);
                mma_fp16(acc[mi][nt], ah[mi], blp);
            }
        if (self_tile) {
            uint32_t al[2][4];
#pragma unroll
            for (int mi = 0; mi < 2; mi++) {
                uint32_t off = (uint32_t)((a_row + mi * 16) * ASTRIDE + k0 + a_kof) * 2;
                ldsm4(al[mi], sb + SM_ALO + off);
            }
#pragma unroll
            for (int mi = 0; mi < 2; mi++)
#pragma unroll
                for (int nt = 0; nt < 4; nt++)
                    mma_fp16(acc[mi][nt], al[mi], &bh[nt >> 1][(nt & 1) * 2]);
        }
    }

    const int g  = lid >> 2;
    const int tg = lid & 3;
#pragma unroll
    for (int mi = 0; mi < 2; mi++) {
#pragma unroll
        for (int hf = 0; hf < 2; hf++) {
            int row = n0 + wr * 32 + mi * 16 + g + hf * 8;
            if (row >= N) continue;
#pragma unroll
            for (int nt = 0; nt < 4; nt++) {
                int cl = wc * 32 + nt * 8 + tg * 2;
                float v0 = acc[mi][nt][hf * 2 + 0];
                float v1 = acc[mi][nt][hf * 2 + 1];
                if (self_tile) {
                    v0 += bias[cl];
                    v1 += bias[cl + 1];
                    if (residual) {
                        v0 += xres[(size_t)row * DFEAT + cl];
                        v1 += xres[(size_t)row * DFEAT + cl + 1];
                    }
                    *(float2*)(outbuf + (size_t)row * DFEAT + cl) = make_float2(v0, v1);
                } else {
                    __half2 hv = __floats2half2_rn(v0, v1);
                    *(__half2*)(g_Yh + (size_t)row * RELCOLS + (cg0 - DFEAT) + cl) = hv;
                }
            }
        }
    }
}

// ---------------------------------------------------------------------------
// CSR aggregation: one warp per dst node; unroll 4 for gather MLP
// ---------------------------------------------------------------------------
__global__ void __launch_bounds__(256) agg_k(float* __restrict__ inout, int N, int relu) {
    const int wid  = threadIdx.x >> 5;
    const int lid  = threadIdx.x & 31;
    const int node = blockIdx.x * 8 + wid;
    if (node >= N) return;

    const int s  = g_indptr[node];
    const int e2 = g_indptr[node + 1];

    float ax = 0.0f, ay = 0.0f;
    const __half* Yh = g_Yh;
    const int co = lid * 2;

    int i = s;
    for (; i + 3 < e2; i += 4) {
        uint32_t p0 = g_edata[i],     p1 = g_edata[i + 1];
        uint32_t p2 = g_edata[i + 2], p3 = g_edata[i + 3];
        __half2 v0 = *(const __half2*)(Yh + (size_t)(p0 & 0xFFFFF) * RELCOLS + ((p0 >> 20) << 6) + co);
        __half2 v1 = *(const __half2*)(Yh + (size_t)(p1 & 0xFFFFF) * RELCOLS + ((p1 >> 20) << 6) + co);
        __half2 v2 = *(const __half2*)(Yh + (size_t)(p2 & 0xFFFFF) * RELCOLS + ((p2 >> 20) << 6) + co);
        __half2 v3 = *(const __half2*)(Yh + (size_t)(p3 & 0xFFFFF) * RELCOLS + ((p3 >> 20) << 6) + co);
        float2 f0 = __half22float2(v0), f1 = __half22float2(v1);
        float2 f2 = __half22float2(v2), f3 = __half22float2(v3);
        ax += (f0.x + f1.x) + (f2.x + f3.x);
        ay += (f0.y + f1.y) + (f2.y + f3.y);
    }
    for (; i < e2; i++) {
        uint32_t p0 = g_edata[i];
        __half2 v0 = *(const __half2*)(Yh + (size_t)(p0 & 0xFFFFF) * RELCOLS + ((p0 >> 20) << 6) + co);
        float2 f0 = __half22float2(v0);
        ax += f0.x;
        ay += f0.y;
    }

    float* p = inout + (size_t)node * DFEAT + co;
    float2 base = *(float2*)p;
    float rx = base.x + ax;
    float ry = base.y + ay;
    if (relu) { rx = fmaxf(rx, 0.0f); ry = fmaxf(ry, 0.0f); }
    *(float2*)p = make_float2(rx, ry);
}

// ---------------------------------------------------------------------------
extern "C" void kernel_launch(void* const* d_in, const int* in_sizes, int n_in,
                              void* d_out, int out_size) {
    const float* x   = (const float*)d_in[0];
    const int*   ei  = (const int*)d_in[1];
    const int*   et  = (const int*)d_in[2];
    const float* W1  = (const float*)d_in[3];
    const float* sw1 = (const float*)d_in[4];
    const float* b1  = (const float*)d_in[5];
    const float* W2  = (const float*)d_in[6];
    const float* sw2 = (const float*)d_in[7];
    const float* b2  = (const float*)d_in[8];
    float* out = (float*)d_out;

    const int N = in_sizes[0] / DFEAT;
    const int E = in_sizes[2];
    const int total4 = N * (DFEAT / 4);
    const int nb = (N + 1023) / 1024;

    float* hptr = nullptr;
    cudaGetSymbolAddress((void**)&hptr, g_h);

    cudaFuncSetAttribute(gemm_mma, cudaFuncAttributeMaxDynamicSharedMemorySize, SMEM_BYTES);

    dim3 gemm_grid((N + 127) / 128, NCOLS / 64);
    int pack_blocks = (NCOLS * DFEAT + 255) / 256;
    int el_blocks   = (total4 + 255) / 256;
    int e_blocks    = (E + 255) / 256;
    int n_blocks    = (N + 255) / 256;
    int agg_blocks  = (N + 7) / 8;

    // ---- CSR build (once, reused by both layers) ----
    zero_cnt<<<n_blocks, 256>>>(N);
    hist_k<<<e_blocks, 256>>>(ei, E);
    scan1<<<nb, 1024>>>(N);
    scan2<<<1, NBLK_MAX>>>(nb);
    scan3<<<nb, 1024>>>(N, E);
    fill_k<<<e_blocks, 256>>>(ei, et, E);

    // ---- layer 1 (residual) ----
    conv_fp16<<<el_blocks, 256>>>(x, total4, 0);
    pack_wb<<<pack_blocks, 256>>>(W1, sw1);
    gemm_mma<<<gemm_grid, 256, SMEM_BYTES>>>(x, b1, hptr, N, 1);
    agg_k<<<agg_blocks, 256>>>(hptr, N, 0);

    // ---- layer 2 (no residual; relu of layer 1 fused into conv) ----
    conv_fp16<<<el_blocks, 256>>>(hptr, total4, 1);
    pack_wb<<<pack_blocks, 256>>>(W2, sw2);
    gemm_mma<<<gemm_grid, 256, SMEM_BYTES>>>(x, b2, out, N, 0);
    agg_k<<<agg_blocks, 256>>>(out, N, 1);
}